// round 6
// baseline (speedup 1.0000x reference)
#include <cuda_runtime.h>
#include <cuda_bf16.h>
#include <cstdint>

#define NMAX 1000000
#define CC 16
#define KS 9
#define TPB 128                 // 4 warps
#define WPC 4
#define GRID_CONV 444           // 148 SMs * 3 CTAs
#define STAGE_DATA 9216         // per-warp: 18 chunks * 512B
#define STAGE_IDX  768          // 144 ints + pad
#define STAGE_BYTES (STAGE_DATA + STAGE_IDX)
#define SMEM_BYTES (WPC * STAGE_BYTES)

typedef unsigned int uint;

// ---------------- device scratch ----------------
__device__ float g_z1[(size_t)NMAX * CC];
__device__ float g_z2[(size_t)NMAX * CC];
__device__ uint4 g_dhl[(size_t)NMAX * 4];   // per row 64B: [hi c0-7 | hi c8-15 | lo c0-7 | lo c8-15]
__device__ uint4 g_ahl[(size_t)NMAX * 4];
__device__ float g_stats[64];               // sum1, sumsq1, sum2, sumsq2

// ---------------- helpers ----------------
__device__ __forceinline__ uint32_t smem_u32(const void* p) {
    uint32_t a;
    asm("{ .reg .u64 t; cvta.to.shared.u64 t, %1; cvt.u32.u64 %0, t; }" : "=r"(a) : "l"(p));
    return a;
}
__device__ __forceinline__ void sts128(uint32_t a, uint4 v) {
    asm volatile("st.shared.v4.b32 [%0], {%1,%2,%3,%4};"
                 :: "r"(a), "r"(v.x), "r"(v.y), "r"(v.z), "r"(v.w) : "memory");
}
__device__ __forceinline__ void sts32(uint32_t a, uint v) {
    asm volatile("st.shared.b32 [%0], %1;" :: "r"(a), "r"(v) : "memory");
}
__device__ __forceinline__ uint lds32(uint32_t a) {
    uint v;
    asm volatile("ld.shared.b32 %0, [%1];" : "=r"(v) : "r"(a));
    return v;
}
__device__ __forceinline__ void ldsm4(uint32_t* a, uint32_t addr) {
    asm volatile("ldmatrix.sync.aligned.m8n8.x4.shared.b16 {%0,%1,%2,%3}, [%4];"
                 : "=r"(a[0]), "=r"(a[1]), "=r"(a[2]), "=r"(a[3]) : "r"(addr));
}
__device__ __forceinline__ void mma16816(float* c, const uint32_t* a, const uint32_t* b) {
    asm volatile("mma.sync.aligned.m16n8k16.row.col.f32.bf16.bf16.f32 "
                 "{%0,%1,%2,%3}, {%4,%5,%6,%7}, {%8,%9}, {%0,%1,%2,%3};"
                 : "+f"(c[0]), "+f"(c[1]), "+f"(c[2]), "+f"(c[3])
                 : "r"(a[0]), "r"(a[1]), "r"(a[2]), "r"(a[3]), "r"(b[0]), "r"(b[1]));
}
__device__ __forceinline__ float leaky(float x) { return fmaxf(x, 0.2f * x); }

__device__ __forceinline__ uint packhl(float x, float y, uint& lo_out) {
    __nv_bfloat16 hx = __float2bfloat16_rn(x);
    __nv_bfloat16 hy = __float2bfloat16_rn(y);
    __nv_bfloat16 lx = __float2bfloat16_rn(x - __bfloat162float(hx));
    __nv_bfloat16 ly = __float2bfloat16_rn(y - __bfloat162float(hy));
    lo_out = (uint)__bfloat16_as_ushort(lx) | ((uint)__bfloat16_as_ushort(ly) << 16);
    return (uint)__bfloat16_as_ushort(hx) | ((uint)__bfloat16_as_ushort(hy) << 16);
}

// split 8 floats -> hi uint4 + lo uint4
__device__ __forceinline__ void split8(const float* v, uint4& hi, uint4& lo) {
    uint l0, l1, l2, l3;
    hi.x = packhl(v[0], v[1], l0);
    hi.y = packhl(v[2], v[3], l1);
    hi.z = packhl(v[4], v[5], l2);
    hi.w = packhl(v[6], v[7], l3);
    lo = make_uint4(l0, l1, l2, l3);
}

// ---------------------------------------------------------------------------
// k0: zero stats + split data -> g_dhl
// ---------------------------------------------------------------------------
__global__ __launch_bounds__(256) void k0_split(const float* __restrict__ data, int N) {
    int g = blockIdx.x * 256 + threadIdx.x;
    if (g < 64) g_stats[g] = 0.0f;
    if (g >= 2 * N) return;
    int p = g >> 1, h = g & 1;
    const float4* s = reinterpret_cast<const float4*>(data) + (size_t)p * 4 + h * 2;
    float4 a = s[0], b = s[1];
    float v[8] = {a.x, a.y, a.z, a.w, b.x, b.y, b.z, b.w};
    uint4 hi, lo;
    split8(v, hi, lo);
    g_dhl[(size_t)p * 4 + h] = hi;
    g_dhl[(size_t)p * 4 + 2 + h] = lo;
}

// ---------------------------------------------------------------------------
// conv via mma.sync, quad-cooperative gather (1 L1 wavefront per row)
// ---------------------------------------------------------------------------
template <bool FIRST>
__global__ __launch_bounds__(TPB, 3) void conv_mma(
    const int* __restrict__ ind, const float* __restrict__ w,
    const float* __restrict__ bias, int N, int ntiles)
{
    extern __shared__ __align__(16) char smraw[];
    const int tid = threadIdx.x, wid = tid >> 5, lane = tid & 31;
    const uint32_t stage = smem_u32(smraw) + (uint32_t)wid * STAGE_BYTES;
    const uint32_t idxs = stage + STAGE_DATA;

    const uint4* __restrict__ src = FIRST ? g_dhl : g_ahl;
    float* __restrict__ zout = FIRST ? g_z1 : g_z2;

    const int t4 = lane & 3;
    const int nrow = lane >> 2;

    // ---- B fragments in registers ----
    uint32_t bh[KS][2][2], bl[KS][2][2];
#pragma unroll
    for (int j = 0; j < KS; ++j) {
#pragma unroll
        for (int nf = 0; nf < 2; ++nf) {
            int n = nf * 8 + nrow;
            int k0 = t4 * 2;
            float w00 = __ldg(w + ((k0 + 0) * CC + n) * KS + j);
            float w01 = __ldg(w + ((k0 + 1) * CC + n) * KS + j);
            float w10 = __ldg(w + ((k0 + 8) * CC + n) * KS + j);
            float w11 = __ldg(w + ((k0 + 9) * CC + n) * KS + j);
            uint lo;
            bh[j][nf][0] = packhl(w00, w01, lo); bl[j][nf][0] = lo;
            bh[j][nf][1] = packhl(w10, w11, lo); bl[j][nf][1] = lo;
        }
    }

    float bia[4] = {0, 0, 0, 0};
    if (FIRST) {
        bia[0] = __ldg(bias + 2 * t4);
        bia[1] = __ldg(bias + 2 * t4 + 1);
        bia[2] = __ldg(bias + 2 * t4 + 8);
        bia[3] = __ldg(bias + 2 * t4 + 9);
    }

    // ldmatrix per-lane address offset within a 512B chunk
    const uint32_t lr = lane & 15;
    const uint32_t lseg = (uint32_t)(lane >> 4) ^ ((lr >> 2) & 1);
    const uint32_t lmoff = lr * 32 + lseg * 16;

    // gather role: quad g = lane>>2 handles rows g, g+8 per iteration; q = quarter
    const int q = lane & 3;
    const int grp = lane >> 2;
    const uint32_t qreg = (q >> 1) ? (uint32_t)(KS * 512) : 0u;  // lo chunks at +4608
    const int qh = q & 1;

    float s[4] = {0, 0, 0, 0}, qq[4] = {0, 0, 0, 0};

    const int wstep = GRID_CONV * WPC;
    for (int t = blockIdx.x * WPC + wid; t < ntiles; t += wstep) {
        const int base = t * 16;

        // ---- stage idx[144]: coalesced ind read, scatter to row order ----
#pragma unroll
        for (int i = 0; i < 5; ++i) {
            int u = i * 32 + lane;
            if (u < 144) {
                int pt = u / KS, j = u - pt * KS;
                int pg = base + pt;
                int v = (pg < N) ? __ldg(ind + (size_t)base * KS + u) : 0;
                sts32(idxs + (uint32_t)(j * 16 + pt) * 4, (uint)v);
            }
        }
        __syncwarp();

        // ---- quad-cooperative gather: 18 iters x 8 rows ----
#pragma unroll
        for (int i = 0; i < 18; ++i) {
            int r = i * 8 + grp;            // row id 0..143
            int pt = r & 15, j = r >> 4;
            int idx = (int)lds32(idxs + (uint32_t)r * 4);
            uint4 v = __ldg(src + (size_t)idx * 4 + q);
            uint32_t x = ((uint32_t)(pt >> 2) & 1u) << 4;
            uint32_t dst = stage + qreg + (uint32_t)j * 512 + (uint32_t)pt * 32 +
                           (((uint32_t)qh << 4) ^ x);
            sts128(dst, v);
        }
        __syncwarp();

        // ---- MMA ----
        float c0[4] = {0, 0, 0, 0}, c1[4] = {0, 0, 0, 0};
#pragma unroll
        for (int j = 0; j < KS; ++j) {
            uint32_t ah[4], al[4];
            ldsm4(ah, stage + (uint32_t)j * 512 + lmoff);
            ldsm4(al, stage + (uint32_t)(KS + j) * 512 + lmoff);
            mma16816(c0, ah, bh[j][0]);
            mma16816(c1, ah, bh[j][1]);
            mma16816(c0, ah, bl[j][0]);
            mma16816(c1, ah, bl[j][1]);
            mma16816(c0, al, bh[j][0]);
            mma16816(c1, al, bh[j][1]);
        }
        __syncwarp();

        // ---- epilogue ----
        int pA = base + nrow;
        int pB = pA + 8;
        float zA0 = c0[0] + bia[0], zA1 = c0[1] + bia[1];
        float zA2 = c1[0] + bia[2], zA3 = c1[1] + bia[3];
        float zB0 = c0[2] + bia[0], zB1 = c0[3] + bia[1];
        float zB2 = c1[2] + bia[2], zB3 = c1[3] + bia[3];

        if (pA < N) {
            float* zr = zout + (size_t)pA * CC + 2 * t4;
            reinterpret_cast<float2*>(zr)[0] = make_float2(zA0, zA1);
            reinterpret_cast<float2*>(zr + 8)[0] = make_float2(zA2, zA3);
            s[0] += zA0; s[1] += zA1; s[2] += zA2; s[3] += zA3;
            qq[0] += zA0 * zA0; qq[1] += zA1 * zA1; qq[2] += zA2 * zA2; qq[3] += zA3 * zA3;
        }
        if (pB < N) {
            float* zr = zout + (size_t)pB * CC + 2 * t4;
            reinterpret_cast<float2*>(zr)[0] = make_float2(zB0, zB1);
            reinterpret_cast<float2*>(zr + 8)[0] = make_float2(zB2, zB3);
            s[0] += zB0; s[1] += zB1; s[2] += zB2; s[3] += zB3;
            qq[0] += zB0 * zB0; qq[1] += zB1 * zB1; qq[2] += zB2 * zB2; qq[3] += zB3 * zB3;
        }
    }

    // ---- stats ----
#pragma unroll
    for (int off = 4; off <= 16; off <<= 1) {
#pragma unroll
        for (int k = 0; k < 4; ++k) {
            s[k] += __shfl_xor_sync(0xffffffffu, s[k], off);
            qq[k] += __shfl_xor_sync(0xffffffffu, qq[k], off);
        }
    }
    if (lane < 4) {
        const int soff = FIRST ? 0 : 32;
        int ch[4] = {2 * lane, 2 * lane + 1, 2 * lane + 8, 2 * lane + 9};
#pragma unroll
        for (int k = 0; k < 4; ++k) {
            atomicAdd(&g_stats[soff + ch[k]], s[k]);
            atomicAdd(&g_stats[soff + 16 + ch[k]], qq[k]);
        }
    }
}

// ---------------------------------------------------------------------------
// k1b: act = leaky(bn1(z1)); split -> g_ahl
// ---------------------------------------------------------------------------
__global__ __launch_bounds__(256) void k1b_actsplit(
    const float* __restrict__ gamma1, const float* __restrict__ beta1, int N, float invN)
{
    __shared__ float as_[CC], cs_[CC];
    if (threadIdx.x < CC) {
        int o = threadIdx.x;
        float mean = g_stats[o] * invN;
        float var = g_stats[16 + o] * invN - mean * mean;
        float a = gamma1[o] * rsqrtf(var + 1e-5f);
        as_[o] = a;
        cs_[o] = fmaf(-mean, a, beta1[o]);
    }
    __syncthreads();
    int g = blockIdx.x * 256 + threadIdx.x;
    if (g >= 2 * N) return;
    int p = g >> 1, h = g & 1;
    const float4* sp = reinterpret_cast<const float4*>(g_z1) + (size_t)p * 4 + h * 2;
    float4 a = sp[0], b = sp[1];
    float v[8] = {a.x, a.y, a.z, a.w, b.x, b.y, b.z, b.w};
#pragma unroll
    for (int k = 0; k < 8; ++k) {
        int c = h * 8 + k;
        v[k] = leaky(fmaf(as_[c], v[k], cs_[c]));
    }
    uint4 hi, lo;
    split8(v, hi, lo);
    g_ahl[(size_t)p * 4 + h] = hi;
    g_ahl[(size_t)p * 4 + 2 + h] = lo;
}

// ---------------------------------------------------------------------------
// k3: out = leaky(bn2(z2) + data)
// ---------------------------------------------------------------------------
__global__ __launch_bounds__(256) void k3_epilogue(
    const float* __restrict__ data, const float* __restrict__ gamma2,
    const float* __restrict__ beta2, float* __restrict__ out, int N, float invN)
{
    __shared__ float a2s[CC], c2s[CC];
    if (threadIdx.x < CC) {
        int o = threadIdx.x;
        float mean = g_stats[32 + o] * invN;
        float var = g_stats[48 + o] * invN - mean * mean;
        float a = gamma2[o] * rsqrtf(var + 1e-5f);
        a2s[o] = a;
        c2s[o] = fmaf(-mean, a, beta2[o]);
    }
    __syncthreads();
    int total4 = N * 4;
    const float4* z4 = reinterpret_cast<const float4*>(g_z2);
    const float4* d4 = reinterpret_cast<const float4*>(data);
    float4* o4 = reinterpret_cast<float4*>(out);
    for (int i = blockIdx.x * blockDim.x + threadIdx.x; i < total4;
         i += gridDim.x * blockDim.x) {
        float4 zv = z4[i];
        float4 dv = d4[i];
        int cb = (i & 3) * 4;
        float4 r;
        r.x = leaky(fmaf(a2s[cb + 0], zv.x, c2s[cb + 0]) + dv.x);
        r.y = leaky(fmaf(a2s[cb + 1], zv.y, c2s[cb + 1]) + dv.y);
        r.z = leaky(fmaf(a2s[cb + 2], zv.z, c2s[cb + 2]) + dv.z);
        r.w = leaky(fmaf(a2s[cb + 3], zv.w, c2s[cb + 3]) + dv.w);
        o4[i] = r;
    }
}

extern "C" void kernel_launch(void* const* d_in, const int* in_sizes, int n_in,
                              void* d_out, int out_size)
{
    const float* data   = (const float*)d_in[0];
    const int*   ind    = (const int*)d_in[1];
    const float* w1     = (const float*)d_in[2];
    const float* b1     = (const float*)d_in[3];
    const float* gamma1 = (const float*)d_in[4];
    const float* beta1  = (const float*)d_in[5];
    const float* w2     = (const float*)d_in[6];
    const float* gamma2 = (const float*)d_in[7];
    const float* beta2  = (const float*)d_in[8];

    int N = in_sizes[0] / CC;
    if (N > NMAX) N = NMAX;
    float invN = 1.0f / (float)N;
    int ntiles = (N + 15) / 16;
    int gsplit = (2 * N + 255) / 256;

    k0_split<<<gsplit, 256>>>(data, N);
    conv_mma<true><<<GRID_CONV, TPB, SMEM_BYTES>>>(ind, w1, b1, N, ntiles);
    k1b_actsplit<<<gsplit, 256>>>(gamma1, beta1, N, invN);
    conv_mma<false><<<GRID_CONV, TPB, SMEM_BYTES>>>(ind, w2, nullptr, N, ntiles);
    k3_epilogue<<<1024, 256>>>(data, gamma2, beta2, (float*)d_out, N, invN);
}

// round 8
// speedup vs baseline: 1.4703x; 1.4703x over previous
#include <cuda_runtime.h>
#include <cuda_bf16.h>
#include <cstdint>

#define NMAX 1000000
#define CC 16
#define KS 9
#define TPB 128                 // 4 warps
#define WPC 4
#define GRID_CONV 592           // 148 SMs * 4 CTAs
#define BSM_BYTES 9216          // 36 entries * 256B
#define WSTRIDE 9856            // per-warp staging (18 chunks * 544B, padded)
#define SMEM_BYTES (BSM_BYTES + WPC * WSTRIDE)   // 48640 < 48KB default limit

typedef unsigned int uint;

// ---------------- device scratch ----------------
__device__ float g_z1[(size_t)NMAX * CC];
__device__ float g_z2[(size_t)NMAX * CC];
__device__ uint4 g_dhl[(size_t)NMAX * 4];   // per row 64B: [hi c0-7 | hi c8-15 | lo c0-7 | lo c8-15]
__device__ uint4 g_ahl[(size_t)NMAX * 4];
__device__ float g_stats[64];               // sum1, sumsq1, sum2, sumsq2

// ---------------- helpers ----------------
__device__ __forceinline__ uint32_t smem_u32(const void* p) {
    uint32_t a;
    asm("{ .reg .u64 t; cvta.to.shared.u64 t, %1; cvt.u32.u64 %0, t; }" : "=r"(a) : "l"(p));
    return a;
}
__device__ __forceinline__ void ldsm4(uint32_t* a, uint32_t addr) {
    asm volatile("ldmatrix.sync.aligned.m8n8.x4.shared.b16 {%0,%1,%2,%3}, [%4];"
                 : "=r"(a[0]), "=r"(a[1]), "=r"(a[2]), "=r"(a[3]) : "r"(addr));
}
__device__ __forceinline__ void lds64(uint32_t* r, uint32_t a) {
    asm volatile("ld.shared.v2.b32 {%0,%1}, [%2];" : "=r"(r[0]), "=r"(r[1]) : "r"(a));
}
__device__ __forceinline__ void mma16816(float* c, const uint32_t* a, const uint32_t* b) {
    asm volatile("mma.sync.aligned.m16n8k16.row.col.f32.bf16.bf16.f32 "
                 "{%0,%1,%2,%3}, {%4,%5,%6,%7}, {%8,%9}, {%0,%1,%2,%3};"
                 : "+f"(c[0]), "+f"(c[1]), "+f"(c[2]), "+f"(c[3])
                 : "r"(a[0]), "r"(a[1]), "r"(a[2]), "r"(a[3]), "r"(b[0]), "r"(b[1]));
}
__device__ __forceinline__ float leaky(float x) { return fmaxf(x, 0.2f * x); }

__device__ __forceinline__ uint packhl(float x, float y, uint& lo_out) {
    __nv_bfloat16 hx = __float2bfloat16_rn(x);
    __nv_bfloat16 hy = __float2bfloat16_rn(y);
    __nv_bfloat16 lx = __float2bfloat16_rn(x - __bfloat162float(hx));
    __nv_bfloat16 ly = __float2bfloat16_rn(y - __bfloat162float(hy));
    lo_out = (uint)__bfloat16_as_ushort(lx) | ((uint)__bfloat16_as_ushort(ly) << 16);
    return (uint)__bfloat16_as_ushort(hx) | ((uint)__bfloat16_as_ushort(hy) << 16);
}
__device__ __forceinline__ void split8(const float* v, uint4& hi, uint4& lo) {
    uint l0, l1, l2, l3;
    hi.x = packhl(v[0], v[1], l0);
    hi.y = packhl(v[2], v[3], l1);
    hi.z = packhl(v[4], v[5], l2);
    hi.w = packhl(v[6], v[7], l3);
    lo = make_uint4(l0, l1, l2, l3);
}

// ---------------------------------------------------------------------------
// k0: zero stats + split data -> g_dhl
// ---------------------------------------------------------------------------
__global__ __launch_bounds__(256) void k0_split(const float* __restrict__ data, int N) {
    int g = blockIdx.x * 256 + threadIdx.x;
    if (g < 64) g_stats[g] = 0.0f;
    if (g >= 2 * N) return;
    int p = g >> 1, h = g & 1;
    const float4* s = reinterpret_cast<const float4*>(data) + (size_t)p * 4 + h * 2;
    float4 a = s[0], b = s[1];
    float v[8] = {a.x, a.y, a.z, a.w, b.x, b.y, b.z, b.w};
    uint4 hi, lo;
    split8(v, hi, lo);
    g_dhl[(size_t)p * 4 + h] = hi;
    g_dhl[(size_t)p * 4 + 2 + h] = lo;
}

// ---------------------------------------------------------------------------
// conv via mma.sync: quad-cooperative gather, shuffle-distributed indices,
// B fragments in shared memory (occupancy), chunk stride 544B (bank spread).
// ---------------------------------------------------------------------------
template <bool FIRST>
__global__ __launch_bounds__(TPB, 4) void conv_mma(
    const int* __restrict__ ind, const float* __restrict__ w,
    const float* __restrict__ bias, int N, int ntiles)
{
    extern __shared__ __align__(16) char smraw[];
    const int tid = threadIdx.x, wid = tid >> 5, lane = tid & 31;
    char* const stage = smraw + BSM_BYTES + wid * WSTRIDE;
    const uint32_t stage32 = smem_u32(stage);
    const uint32_t Blane = smem_u32(smraw) + (uint32_t)lane * 8u;

    const uint4* __restrict__ src = FIRST ? g_dhl : g_ahl;
    float* __restrict__ zout = FIRST ? g_z1 : g_z2;

    const int t4 = lane & 3;
    const int nrow = lane >> 2;
    const int q = lane & 3;
    const int grp = lane >> 2;

    // ---- warp 0 stages B fragments (hi & lo) into shared ----
    if (wid == 0) {
#pragma unroll
        for (int j = 0; j < KS; ++j) {
#pragma unroll
            for (int nf = 0; nf < 2; ++nf) {
                int n = nf * 8 + nrow;
                int k0 = t4 * 2;
                float w00 = __ldg(w + ((k0 + 0) * CC + n) * KS + j);
                float w01 = __ldg(w + ((k0 + 1) * CC + n) * KS + j);
                float w10 = __ldg(w + ((k0 + 8) * CC + n) * KS + j);
                float w11 = __ldg(w + ((k0 + 9) * CC + n) * KS + j);
                uint l0, l1;
                uint h0 = packhl(w00, w01, l0);
                uint h1 = packhl(w10, w11, l1);
                // entry e = j*4 + term*2 + nf  (term 0=hi,1=lo), 256B each
                *reinterpret_cast<uint2*>(smraw + (j * 4 + nf) * 256 + lane * 8) =
                    make_uint2(h0, h1);
                *reinterpret_cast<uint2*>(smraw + (j * 4 + 2 + nf) * 256 + lane * 8) =
                    make_uint2(l0, l1);
            }
        }
    }
    __syncthreads();

    float bia[4] = {0, 0, 0, 0};
    if (FIRST) {
        bia[0] = __ldg(bias + 2 * t4);
        bia[1] = __ldg(bias + 2 * t4 + 1);
        bia[2] = __ldg(bias + 2 * t4 + 8);
        bia[3] = __ldg(bias + 2 * t4 + 9);
    }

    // ldmatrix per-lane offset within a 544B chunk (layout inside chunk = verified R5)
    const uint32_t lr = lane & 15;
    const uint32_t lseg = (uint32_t)(lane >> 4) ^ ((lr >> 2) & 1);
    const uint32_t lmoff = lr * 32 + lseg * 16;

    const uint32_t qh = (uint32_t)(q & 1);
    const int qlo = (q >> 1) ? 9 : 0;   // lo quarters go to chunks 9..17

    float s[4] = {0, 0, 0, 0}, qq[4] = {0, 0, 0, 0};
    const unsigned indmax = (unsigned)N * KS - 1u;

    const int wstep = GRID_CONV * WPC;
    for (int t = blockIdx.x * WPC + wid; t < ntiles; t += wstep) {
        const int base = t * 16;

        // ---- coalesced ind load into registers ----
        int iv[5];
#pragma unroll
        for (int i = 0; i < 5; ++i) {
            unsigned u = (unsigned)(i * 32 + lane);
            unsigned off = (unsigned)base * KS + (u < 144u ? u : 0u);
            iv[i] = __ldg(ind + (off <= indmax ? off : indmax));
        }
        // ---- distribute to quads via shuffles (u = i*8 + grp) ----
        int idx[18];
#pragma unroll
        for (int i = 0; i < 18; ++i)
            idx[i] = __shfl_sync(0xffffffffu, iv[i >> 2], ((i & 3) << 3) + grp);

        // ---- quad-cooperative gather, 2 batches of 9 (MLP=9 each) ----
#pragma unroll
        for (int b = 0; b < 2; ++b) {
            uint4 v[9];
#pragma unroll
            for (int k = 0; k < 9; ++k)
                v[k] = __ldg(src + (size_t)(unsigned)idx[b * 9 + k] * 4 + q);
#pragma unroll
            for (int k = 0; k < 9; ++k) {
                int u = (b * 9 + k) * 8 + grp;
                int pt = (u * 57) >> 9;      // u/9 (valid u<512)
                int j = u - pt * 9;
                uint32_t off = (uint32_t)(qlo + j) * 544u + (uint32_t)pt * 32u +
                               (((qh ^ (((uint32_t)pt >> 2) & 1u)) << 4));
                *reinterpret_cast<uint4*>(stage + off) = v[k];
            }
        }
        __syncwarp();

        // ---- MMA: 9 chunks x (Ahi*Bhi + Ahi*Blo + Alo*Bhi) x 2 n-frags ----
        float c0[4] = {0, 0, 0, 0}, c1[4] = {0, 0, 0, 0};
#pragma unroll
        for (int j = 0; j < KS; ++j) {
            uint32_t ah[4], al[4];
            ldsm4(ah, stage32 + (uint32_t)j * 544u + lmoff);
            ldsm4(al, stage32 + (uint32_t)(9 + j) * 544u + lmoff);
            uint32_t bh0[2], bh1[2], bl0[2], bl1[2];
            lds64(bh0, Blane + (uint32_t)(j * 4 + 0) * 256u);
            lds64(bh1, Blane + (uint32_t)(j * 4 + 1) * 256u);
            lds64(bl0, Blane + (uint32_t)(j * 4 + 2) * 256u);
            lds64(bl1, Blane + (uint32_t)(j * 4 + 3) * 256u);
            mma16816(c0, ah, bh0);
            mma16816(c1, ah, bh1);
            mma16816(c0, ah, bl0);
            mma16816(c1, ah, bl1);
            mma16816(c0, al, bh0);
            mma16816(c1, al, bh1);
        }
        __syncwarp();

        // ---- epilogue: bias, z store, stats ----
        int pA = base + nrow;
        int pB = pA + 8;
        float zA0 = c0[0] + bia[0], zA1 = c0[1] + bia[1];
        float zA2 = c1[0] + bia[2], zA3 = c1[1] + bia[3];
        float zB0 = c0[2] + bia[0], zB1 = c0[3] + bia[1];
        float zB2 = c1[2] + bia[2], zB3 = c1[3] + bia[3];

        if (pA < N) {
            float* zr = zout + (size_t)pA * CC + 2 * t4;
            reinterpret_cast<float2*>(zr)[0] = make_float2(zA0, zA1);
            reinterpret_cast<float2*>(zr + 8)[0] = make_float2(zA2, zA3);
            s[0] += zA0; s[1] += zA1; s[2] += zA2; s[3] += zA3;
            qq[0] += zA0 * zA0; qq[1] += zA1 * zA1; qq[2] += zA2 * zA2; qq[3] += zA3 * zA3;
        }
        if (pB < N) {
            float* zr = zout + (size_t)pB * CC + 2 * t4;
            reinterpret_cast<float2*>(zr)[0] = make_float2(zB0, zB1);
            reinterpret_cast<float2*>(zr + 8)[0] = make_float2(zB2, zB3);
            s[0] += zB0; s[1] += zB1; s[2] += zB2; s[3] += zB3;
            qq[0] += zB0 * zB0; qq[1] += zB1 * zB1; qq[2] += zB2 * zB2; qq[3] += zB3 * zB3;
        }
    }

    // ---- stats: butterfly over lanes sharing t4, then 4 atomics/lane ----
#pragma unroll
    for (int off = 4; off <= 16; off <<= 1) {
#pragma unroll
        for (int k = 0; k < 4; ++k) {
            s[k] += __shfl_xor_sync(0xffffffffu, s[k], off);
            qq[k] += __shfl_xor_sync(0xffffffffu, qq[k], off);
        }
    }
    if (lane < 4) {
        const int soff = FIRST ? 0 : 32;
        int ch[4] = {2 * lane, 2 * lane + 1, 2 * lane + 8, 2 * lane + 9};
#pragma unroll
        for (int k = 0; k < 4; ++k) {
            atomicAdd(&g_stats[soff + ch[k]], s[k]);
            atomicAdd(&g_stats[soff + 16 + ch[k]], qq[k]);
        }
    }
}

// ---------------------------------------------------------------------------
// k1b: act = leaky(bn1(z1)); split -> g_ahl
// ---------------------------------------------------------------------------
__global__ __launch_bounds__(256) void k1b_actsplit(
    const float* __restrict__ gamma1, const float* __restrict__ beta1, int N, float invN)
{
    __shared__ float as_[CC], cs_[CC];
    if (threadIdx.x < CC) {
        int o = threadIdx.x;
        float mean = g_stats[o] * invN;
        float var = g_stats[16 + o] * invN - mean * mean;
        float a = gamma1[o] * rsqrtf(var + 1e-5f);
        as_[o] = a;
        cs_[o] = fmaf(-mean, a, beta1[o]);
    }
    __syncthreads();
    int g = blockIdx.x * 256 + threadIdx.x;
    if (g >= 2 * N) return;
    int p = g >> 1, h = g & 1;
    const float4* sp = reinterpret_cast<const float4*>(g_z1) + (size_t)p * 4 + h * 2;
    float4 a = sp[0], b = sp[1];
    float v[8] = {a.x, a.y, a.z, a.w, b.x, b.y, b.z, b.w};
#pragma unroll
    for (int k = 0; k < 8; ++k) {
        int c = h * 8 + k;
        v[k] = leaky(fmaf(as_[c], v[k], cs_[c]));
    }
    uint4 hi, lo;
    split8(v, hi, lo);
    g_ahl[(size_t)p * 4 + h] = hi;
    g_ahl[(size_t)p * 4 + 2 + h] = lo;
}

// ---------------------------------------------------------------------------
// k3: out = leaky(bn2(z2) + data)
// ---------------------------------------------------------------------------
__global__ __launch_bounds__(256) void k3_epilogue(
    const float* __restrict__ data, const float* __restrict__ gamma2,
    const float* __restrict__ beta2, float* __restrict__ out, int N, float invN)
{
    __shared__ float a2s[CC], c2s[CC];
    if (threadIdx.x < CC) {
        int o = threadIdx.x;
        float mean = g_stats[32 + o] * invN;
        float var = g_stats[48 + o] * invN - mean * mean;
        float a = gamma2[o] * rsqrtf(var + 1e-5f);
        a2s[o] = a;
        c2s[o] = fmaf(-mean, a, beta2[o]);
    }
    __syncthreads();
    int total4 = N * 4;
    const float4* z4 = reinterpret_cast<const float4*>(g_z2);
    const float4* d4 = reinterpret_cast<const float4*>(data);
    float4* o4 = reinterpret_cast<float4*>(out);
    for (int i = blockIdx.x * blockDim.x + threadIdx.x; i < total4;
         i += gridDim.x * blockDim.x) {
        float4 zv = z4[i];
        float4 dv = d4[i];
        int cb = (i & 3) * 4;
        float4 r;
        r.x = leaky(fmaf(a2s[cb + 0], zv.x, c2s[cb + 0]) + dv.x);
        r.y = leaky(fmaf(a2s[cb + 1], zv.y, c2s[cb + 1]) + dv.y);
        r.z = leaky(fmaf(a2s[cb + 2], zv.z, c2s[cb + 2]) + dv.z);
        r.w = leaky(fmaf(a2s[cb + 3], zv.w, c2s[cb + 3]) + dv.w);
        o4[i] = r;
    }
}

extern "C" void kernel_launch(void* const* d_in, const int* in_sizes, int n_in,
                              void* d_out, int out_size)
{
    const float* data   = (const float*)d_in[0];
    const int*   ind    = (const int*)d_in[1];
    const float* w1     = (const float*)d_in[2];
    const float* b1     = (const float*)d_in[3];
    const float* gamma1 = (const float*)d_in[4];
    const float* beta1  = (const float*)d_in[5];
    const float* w2     = (const float*)d_in[6];
    const float* gamma2 = (const float*)d_in[7];
    const float* beta2  = (const float*)d_in[8];

    int N = in_sizes[0] / CC;
    if (N > NMAX) N = NMAX;
    float invN = 1.0f / (float)N;
    int ntiles = (N + 15) / 16;
    int gsplit = (2 * N + 255) / 256;

    k0_split<<<gsplit, 256>>>(data, N);
    conv_mma<true><<<GRID_CONV, TPB, SMEM_BYTES>>>(ind, w1, b1, N, ntiles);
    k1b_actsplit<<<gsplit, 256>>>(gamma1, beta1, N, invN);
    conv_mma<false><<<GRID_CONV, TPB, SMEM_BYTES>>>(ind, w2, nullptr, N, ntiles);
    k3_epilogue<<<1024, 256>>>(data, gamma2, beta2, (float*)d_out, N, invN);
}

// round 10
// speedup vs baseline: 2.4857x; 1.6907x over previous
#include <cuda_runtime.h>
#include <cuda_bf16.h>
#include <cstdint>

#define NMAX 1000000
#define CC 16
#define KS 9
#define TPB 128                 // 4 warps
#define WPC 4
#define GRID_CONV 592           // 148 SMs * 4 CTAs
#define CH 544                  // staging chunk stride (S=68 == 4 mod 16 -> conflict-free STS)
#define BSM 9472                // B frags 9*1024 + coeff 128 + pad
#define WSTRIDE (18 * CH)       // 9792 per warp
#define SMEM_BYTES (BSM + WPC * WSTRIDE)   // 48640 < 49152

typedef unsigned int uint;

// ---------------- device scratch ----------------
__device__ float g_z1[(size_t)NMAX * CC];
__device__ float g_z2[(size_t)NMAX * CC];
__device__ float g_stats[64];   // sum1, sumsq1, sum2, sumsq2

// ---------------- helpers ----------------
__device__ __forceinline__ uint32_t smem_u32(const void* p) {
    uint32_t a;
    asm("{ .reg .u64 t; cvta.to.shared.u64 t, %1; cvt.u32.u64 %0, t; }" : "=r"(a) : "l"(p));
    return a;
}
__device__ __forceinline__ void ldsm4(uint32_t* a, uint32_t addr) {
    asm volatile("ldmatrix.sync.aligned.m8n8.x4.shared.b16 {%0,%1,%2,%3}, [%4];"
                 : "=r"(a[0]), "=r"(a[1]), "=r"(a[2]), "=r"(a[3]) : "r"(addr));
}
__device__ __forceinline__ void mma16816(float* c, const uint32_t* a, uint32_t b0, uint32_t b1) {
    asm volatile("mma.sync.aligned.m16n8k16.row.col.f32.bf16.bf16.f32 "
                 "{%0,%1,%2,%3}, {%4,%5,%6,%7}, {%8,%9}, {%0,%1,%2,%3};"
                 : "+f"(c[0]), "+f"(c[1]), "+f"(c[2]), "+f"(c[3])
                 : "r"(a[0]), "r"(a[1]), "r"(a[2]), "r"(a[3]), "r"(b0), "r"(b1));
}
__device__ __forceinline__ float leaky(float x) { return fmaxf(x, 0.2f * x); }

__device__ __forceinline__ uint bits2(__nv_bfloat162 v) {
    return *reinterpret_cast<uint*>(&v);
}
__device__ __forceinline__ uint packhl(float x, float y, uint& lo_out) {
    __nv_bfloat16 hx = __float2bfloat16_rn(x);
    __nv_bfloat16 hy = __float2bfloat16_rn(y);
    __nv_bfloat16 lx = __float2bfloat16_rn(x - __bfloat162float(hx));
    __nv_bfloat16 ly = __float2bfloat16_rn(y - __bfloat162float(hy));
    lo_out = (uint)__bfloat16_as_ushort(lx) | ((uint)__bfloat16_as_ushort(ly) << 16);
    return (uint)__bfloat16_as_ushort(hx) | ((uint)__bfloat16_as_ushort(hy) << 16);
}
// split float4 -> 8B hi + 8B lo (bf16x4 each, channel order preserved)
__device__ __forceinline__ void split4(float4 v, uint2& hi, uint2& lo) {
    __nv_bfloat162 h0 = __float22bfloat162_rn(make_float2(v.x, v.y));
    __nv_bfloat162 h1 = __float22bfloat162_rn(make_float2(v.z, v.w));
    float2 f0 = __bfloat1622float2(h0), f1 = __bfloat1622float2(h1);
    __nv_bfloat162 l0 = __float22bfloat162_rn(make_float2(v.x - f0.x, v.y - f0.y));
    __nv_bfloat162 l1 = __float22bfloat162_rn(make_float2(v.z - f1.x, v.w - f1.y));
    hi = make_uint2(bits2(h0), bits2(h1));
    lo = make_uint2(bits2(l0), bits2(l1));
}

// ---------------------------------------------------------------------------
// k0: zero the stats accumulators
// ---------------------------------------------------------------------------
__global__ void k0_zero() {
    if (threadIdx.x < 64) g_stats[threadIdx.x] = 0.0f;
}

// ---------------------------------------------------------------------------
// conv via mma.sync: fp32 gather + in-register hi/lo split; conflict-free STS;
// B frags via single LDS.128 per chunk; ind prefetch one tile ahead.
// FIRST: src=data, +bias, out g_z1, stats[0:32)
// else : src=g_z1, BN1+leaky fused, out g_z2, stats[32:64)
// ---------------------------------------------------------------------------
template <bool FIRST>
__global__ __launch_bounds__(TPB, 4) void conv_mma(
    const float* __restrict__ src_ext, const int* __restrict__ ind,
    const float* __restrict__ w, const float* __restrict__ bias,
    const float* __restrict__ gamma, const float* __restrict__ beta,
    int N, int ntiles, float invN)
{
    extern __shared__ __align__(16) char smraw[];
    const int tid = threadIdx.x, wid = tid >> 5, lane = tid & 31;
    char* const smB = smraw;                      // 9 j * 1024B (hi 512 | lo 512)
    float* const coefA = reinterpret_cast<float*>(smraw + 9216);
    float* const coefC = coefA + CC;
    char* const stage = smraw + BSM + wid * WSTRIDE;
    const uint32_t stage32 = smem_u32(stage);

    const float4* __restrict__ src =
        FIRST ? reinterpret_cast<const float4*>(src_ext)
              : reinterpret_cast<const float4*>(g_z1);
    float* __restrict__ zout = FIRST ? g_z1 : g_z2;

    const int t4 = lane & 3;
    const int nrow = lane >> 2;
    const int q = lane & 3;
    const int grp = lane >> 2;

    // ---- warp 0 stages B fragments (hi & lo) ----
    if (wid == 0) {
#pragma unroll
        for (int j = 0; j < KS; ++j) {
            uint h[4], l[4];
#pragma unroll
            for (int nf = 0; nf < 2; ++nf) {
                int n = nf * 8 + nrow;
                int k0 = t4 * 2;
                float w00 = __ldg(w + ((k0 + 0) * CC + n) * KS + j);
                float w01 = __ldg(w + ((k0 + 1) * CC + n) * KS + j);
                float w10 = __ldg(w + ((k0 + 8) * CC + n) * KS + j);
                float w11 = __ldg(w + ((k0 + 9) * CC + n) * KS + j);
                h[nf * 2 + 0] = packhl(w00, w01, l[nf * 2 + 0]);
                h[nf * 2 + 1] = packhl(w10, w11, l[nf * 2 + 1]);
            }
            // layout: {nf0.b0, nf0.b1, nf1.b0, nf1.b1}
            *reinterpret_cast<uint4*>(smB + j * 1024 + lane * 16) =
                make_uint4(h[0], h[1], h[2], h[3]);
            *reinterpret_cast<uint4*>(smB + j * 1024 + 512 + lane * 16) =
                make_uint4(l[0], l[1], l[2], l[3]);
        }
    }
    if (!FIRST && tid < CC) {
        float mean = g_stats[tid] * invN;
        float var = g_stats[16 + tid] * invN - mean * mean;
        float a = __ldg(gamma + tid) * rsqrtf(var + 1e-5f);
        coefA[tid] = a;
        coefC[tid] = fmaf(-mean, a, __ldg(beta + tid));
    }
    __syncthreads();

    // per-lane BN coeffs for source channels 4q..4q+3 (conv2 only)
    float a1v[4], c1v[4];
    if (!FIRST) {
#pragma unroll
        for (int k = 0; k < 4; ++k) { a1v[k] = coefA[4 * q + k]; c1v[k] = coefC[4 * q + k]; }
    }
    float bia[4] = {0, 0, 0, 0};
    if (FIRST) {
        bia[0] = __ldg(bias + 2 * t4);
        bia[1] = __ldg(bias + 2 * t4 + 1);
        bia[2] = __ldg(bias + 2 * t4 + 8);
        bia[3] = __ldg(bias + 2 * t4 + 9);
    }

    // ldmatrix per-lane offset within a CH-strided chunk (R5-verified xor layout)
    const uint32_t lr = lane & 15;
    const uint32_t lseg = (uint32_t)(lane >> 4) ^ ((lr >> 2) & 1);
    const uint32_t lmoff = lr * 32 + lseg * 16;

    float s[4] = {0, 0, 0, 0}, qq[4] = {0, 0, 0, 0};
    const unsigned indmax = (unsigned)N * KS - 1u;
    const int wstep = GRID_CONV * WPC;

    int t = blockIdx.x * WPC + wid;
    int iv[5];
    if (t < ntiles) {
#pragma unroll
        for (int i = 0; i < 5; ++i) {
            unsigned u = (unsigned)(i * 32 + lane);
            unsigned off = (unsigned)(t * 16) * KS + (u < 144u ? u : 0u);
            iv[i] = __ldg(ind + (off <= indmax ? off : indmax));
        }
    }

    for (; t < ntiles; t += wstep) {
        const int base = t * 16;

        // ---- gather+split+STS, 2 batches of 9 (MLP=9) ----
#pragma unroll
        for (int b = 0; b < 2; ++b) {
            int idx[9];
#pragma unroll
            for (int k = 0; k < 9; ++k) {
                int i = b * 9 + k;
                idx[k] = __shfl_sync(0xffffffffu, iv[i >> 2], ((i & 3) << 3) + grp);
            }
            float4 v[9];
#pragma unroll
            for (int k = 0; k < 9; ++k)
                v[k] = __ldg(src + (size_t)(unsigned)idx[k] * 4 + q);
#pragma unroll
            for (int k = 0; k < 9; ++k) {
                float4 x = v[k];
                if (!FIRST) {
                    x.x = leaky(fmaf(a1v[0], x.x, c1v[0]));
                    x.y = leaky(fmaf(a1v[1], x.y, c1v[1]));
                    x.z = leaky(fmaf(a1v[2], x.z, c1v[2]));
                    x.w = leaky(fmaf(a1v[3], x.w, c1v[3]));
                }
                uint2 hi, lo;
                split4(x, hi, lo);
                int u = (b * 9 + k) * 8 + grp;
                int pt = (u * 57) >> 9;        // u/9
                int j = u - pt * 9;
                uint32_t p = ((uint32_t)pt >> 2) & 1u;
                uint32_t off = (uint32_t)j * CH + (uint32_t)pt * 32u +
                               (((uint32_t)q * 8u) ^ (p << 4));
                *reinterpret_cast<uint2*>(stage + off) = hi;
                *reinterpret_cast<uint2*>(stage + 9 * CH + off) = lo;
            }
        }

        // ---- prefetch next tile's indices (overlaps MMA latency) ----
        int tn = t + wstep;
        int ivn[5];
        if (tn < ntiles) {
#pragma unroll
            for (int i = 0; i < 5; ++i) {
                unsigned u = (unsigned)(i * 32 + lane);
                unsigned off = (unsigned)(tn * 16) * KS + (u < 144u ? u : 0u);
                ivn[i] = __ldg(ind + (off <= indmax ? off : indmax));
            }
        }
        __syncwarp();

        // ---- MMA: 9 chunks x (Ahi*Bhi + Ahi*Blo + Alo*Bhi) x 2 n-frags ----
        float c0[4] = {0, 0, 0, 0}, c1[4] = {0, 0, 0, 0};
#pragma unroll
        for (int j = 0; j < KS; ++j) {
            uint32_t ah[4], al[4];
            ldsm4(ah, stage32 + (uint32_t)j * CH + lmoff);
            ldsm4(al, stage32 + (uint32_t)(9 + j) * CH + lmoff);
            uint4 bh = *reinterpret_cast<const uint4*>(smB + j * 1024 + lane * 16);
            uint4 bl = *reinterpret_cast<const uint4*>(smB + j * 1024 + 512 + lane * 16);
            mma16816(c0, ah, bh.x, bh.y);
            mma16816(c1, ah, bh.z, bh.w);
            mma16816(c0, ah, bl.x, bl.y);
            mma16816(c1, ah, bl.z, bl.w);
            mma16816(c0, al, bh.x, bh.y);
            mma16816(c1, al, bh.z, bh.w);
        }
        __syncwarp();

        // ---- epilogue: bias, z store, stats ----
        int pA = base + nrow;
        int pB = pA + 8;
        float zA0 = c0[0] + bia[0], zA1 = c0[1] + bia[1];
        float zA2 = c1[0] + bia[2], zA3 = c1[1] + bia[3];
        float zB0 = c0[2] + bia[0], zB1 = c0[3] + bia[1];
        float zB2 = c1[2] + bia[2], zB3 = c1[3] + bia[3];

        if (pA < N) {
            float* zr = zout + (size_t)pA * CC + 2 * t4;
            reinterpret_cast<float2*>(zr)[0] = make_float2(zA0, zA1);
            reinterpret_cast<float2*>(zr + 8)[0] = make_float2(zA2, zA3);
            s[0] += zA0; s[1] += zA1; s[2] += zA2; s[3] += zA3;
            qq[0] += zA0 * zA0; qq[1] += zA1 * zA1; qq[2] += zA2 * zA2; qq[3] += zA3 * zA3;
        }
        if (pB < N) {
            float* zr = zout + (size_t)pB * CC + 2 * t4;
            reinterpret_cast<float2*>(zr)[0] = make_float2(zB0, zB1);
            reinterpret_cast<float2*>(zr + 8)[0] = make_float2(zB2, zB3);
            s[0] += zB0; s[1] += zB1; s[2] += zB2; s[3] += zB3;
            qq[0] += zB0 * zB0; qq[1] += zB1 * zB1; qq[2] += zB2 * zB2; qq[3] += zB3 * zB3;
        }

#pragma unroll
        for (int i = 0; i < 5; ++i) iv[i] = ivn[i];
    }

    // ---- stats: butterfly over lanes sharing t4, then 4 atomics/lane ----
#pragma unroll
    for (int off = 4; off <= 16; off <<= 1) {
#pragma unroll
        for (int k = 0; k < 4; ++k) {
            s[k] += __shfl_xor_sync(0xffffffffu, s[k], off);
            qq[k] += __shfl_xor_sync(0xffffffffu, qq[k], off);
        }
    }
    if (lane < 4) {
        const int soff = FIRST ? 0 : 32;
        int ch[4] = {2 * lane, 2 * lane + 1, 2 * lane + 8, 2 * lane + 9};
#pragma unroll
        for (int k = 0; k < 4; ++k) {
            atomicAdd(&g_stats[soff + ch[k]], s[k]);
            atomicAdd(&g_stats[soff + 16 + ch[k]], qq[k]);
        }
    }
}

// ---------------------------------------------------------------------------
// k3: out = leaky(bn2(z2) + data)
// ---------------------------------------------------------------------------
__global__ __launch_bounds__(256) void k3_epilogue(
    const float* __restrict__ data, const float* __restrict__ gamma2,
    const float* __restrict__ beta2, float* __restrict__ out, int N, float invN)
{
    __shared__ float a2s[CC], c2s[CC];
    if (threadIdx.x < CC) {
        int o = threadIdx.x;
        float mean = g_stats[32 + o] * invN;
        float var = g_stats[48 + o] * invN - mean * mean;
        float a = gamma2[o] * rsqrtf(var + 1e-5f);
        a2s[o] = a;
        c2s[o] = fmaf(-mean, a, beta2[o]);
    }
    __syncthreads();
    int total4 = N * 4;
    const float4* z4 = reinterpret_cast<const float4*>(g_z2);
    const float4* d4 = reinterpret_cast<const float4*>(data);
    float4* o4 = reinterpret_cast<float4*>(out);
    for (int i = blockIdx.x * blockDim.x + threadIdx.x; i < total4;
         i += gridDim.x * blockDim.x) {
        float4 zv = z4[i];
        float4 dv = d4[i];
        int cb = (i & 3) * 4;
        float4 r;
        r.x = leaky(fmaf(a2s[cb + 0], zv.x, c2s[cb + 0]) + dv.x);
        r.y = leaky(fmaf(a2s[cb + 1], zv.y, c2s[cb + 1]) + dv.y);
        r.z = leaky(fmaf(a2s[cb + 2], zv.z, c2s[cb + 2]) + dv.z);
        r.w = leaky(fmaf(a2s[cb + 3], zv.w, c2s[cb + 3]) + dv.w);
        o4[i] = r;
    }
}

extern "C" void kernel_launch(void* const* d_in, const int* in_sizes, int n_in,
                              void* d_out, int out_size)
{
    const float* data   = (const float*)d_in[0];
    const int*   ind    = (const int*)d_in[1];
    const float* w1     = (const float*)d_in[2];
    const float* b1     = (const float*)d_in[3];
    const float* gamma1 = (const float*)d_in[4];
    const float* beta1  = (const float*)d_in[5];
    const float* w2     = (const float*)d_in[6];
    const float* gamma2 = (const float*)d_in[7];
    const float* beta2  = (const float*)d_in[8];

    int N = in_sizes[0] / CC;
    if (N > NMAX) N = NMAX;
    float invN = 1.0f / (float)N;
    int ntiles = (N + 15) / 16;

    k0_zero<<<1, 64>>>();
    conv_mma<true><<<GRID_CONV, TPB, SMEM_BYTES>>>(
        data, ind, w1, b1, nullptr, nullptr, N, ntiles, invN);
    conv_mma<false><<<GRID_CONV, TPB, SMEM_BYTES>>>(
        data, ind, w2, nullptr, gamma1, beta1, N, ntiles, invN);
    k3_epilogue<<<1024, 256>>>(data, gamma2, beta2, (float*)d_out, N, invN);
}

// round 11
// speedup vs baseline: 2.6679x; 1.0733x over previous
#include <cuda_runtime.h>
#include <cuda_bf16.h>
#include <cstdint>

#define NMAX 1000000
#define CC 16
#define KS 9
#define TPB 128                 // 4 warps
#define WPC 4
#define GRID_CONV 444           // 148 SMs * 3 CTAs
#define CH 544                  // staging chunk stride (conflict-free STS, verified R9/R10)
#define COEF 128                // BN coeff region
#define WSTRIDE (18 * CH)       // 9792 per warp
#define SMEM_BYTES (COEF + WPC * WSTRIDE)   // 39296

typedef unsigned int uint;

// ---------------- device scratch ----------------
__device__ float g_z1[(size_t)NMAX * CC];
__device__ float g_z2[(size_t)NMAX * CC];
__device__ float g_stats[64];   // sum1, sumsq1, sum2, sumsq2

// ---------------- helpers ----------------
__device__ __forceinline__ uint32_t smem_u32(const void* p) {
    uint32_t a;
    asm("{ .reg .u64 t; cvta.to.shared.u64 t, %1; cvt.u32.u64 %0, t; }" : "=r"(a) : "l"(p));
    return a;
}
__device__ __forceinline__ void ldsm4(uint32_t* a, uint32_t addr) {
    asm volatile("ldmatrix.sync.aligned.m8n8.x4.shared.b16 {%0,%1,%2,%3}, [%4];"
                 : "=r"(a[0]), "=r"(a[1]), "=r"(a[2]), "=r"(a[3]) : "r"(addr));
}
__device__ __forceinline__ void mma16816(float* c, const uint32_t* a, uint32_t b0, uint32_t b1) {
    asm volatile("mma.sync.aligned.m16n8k16.row.col.f32.bf16.bf16.f32 "
                 "{%0,%1,%2,%3}, {%4,%5,%6,%7}, {%8,%9}, {%0,%1,%2,%3};"
                 : "+f"(c[0]), "+f"(c[1]), "+f"(c[2]), "+f"(c[3])
                 : "r"(a[0]), "r"(a[1]), "r"(a[2]), "r"(a[3]), "r"(b0), "r"(b1));
}
__device__ __forceinline__ float leaky(float x) { return fmaxf(x, 0.2f * x); }

__device__ __forceinline__ uint bits2(__nv_bfloat162 v) {
    return *reinterpret_cast<uint*>(&v);
}
__device__ __forceinline__ uint packhl(float x, float y, uint& lo_out) {
    __nv_bfloat16 hx = __float2bfloat16_rn(x);
    __nv_bfloat16 hy = __float2bfloat16_rn(y);
    __nv_bfloat16 lx = __float2bfloat16_rn(x - __bfloat162float(hx));
    __nv_bfloat16 ly = __float2bfloat16_rn(y - __bfloat162float(hy));
    lo_out = (uint)__bfloat16_as_ushort(lx) | ((uint)__bfloat16_as_ushort(ly) << 16);
    return (uint)__bfloat16_as_ushort(hx) | ((uint)__bfloat16_as_ushort(hy) << 16);
}
// split float4 -> 8B hi + 8B lo (bf16x4 each, channel order preserved)
__device__ __forceinline__ void split4(float4 v, uint2& hi, uint2& lo) {
    __nv_bfloat162 h0 = __float22bfloat162_rn(make_float2(v.x, v.y));
    __nv_bfloat162 h1 = __float22bfloat162_rn(make_float2(v.z, v.w));
    float2 f0 = __bfloat1622float2(h0), f1 = __bfloat1622float2(h1);
    __nv_bfloat162 l0 = __float22bfloat162_rn(make_float2(v.x - f0.x, v.y - f0.y));
    __nv_bfloat162 l1 = __float22bfloat162_rn(make_float2(v.z - f1.x, v.w - f1.y));
    hi = make_uint2(bits2(h0), bits2(h1));
    lo = make_uint2(bits2(l0), bits2(l1));
}

// ---------------------------------------------------------------------------
// k0: zero the stats accumulators
// ---------------------------------------------------------------------------
__global__ void k0_zero() {
    if (threadIdx.x < 64) g_stats[threadIdx.x] = 0.0f;
}

// ---------------------------------------------------------------------------
// conv via mma.sync: fp32 gather + in-register hi/lo split; conflict-free STS;
// B fragments resident in registers (tile-invariant -> zero per-tile L1 cost).
// FIRST: src=data, +bias, out g_z1, stats[0:32)
// else : src=g_z1, BN1+leaky fused, out g_z2, stats[32:64)
// ---------------------------------------------------------------------------
template <bool FIRST>
__global__ __launch_bounds__(TPB, 3) void conv_mma(
    const float* __restrict__ src_ext, const int* __restrict__ ind,
    const float* __restrict__ w, const float* __restrict__ bias,
    const float* __restrict__ gamma, const float* __restrict__ beta,
    int N, int ntiles, float invN)
{
    extern __shared__ __align__(16) char smraw[];
    const int tid = threadIdx.x, wid = tid >> 5, lane = tid & 31;
    float* const coefA = reinterpret_cast<float*>(smraw);
    float* const coefC = coefA + CC;
    char* const stage = smraw + COEF + wid * WSTRIDE;
    const uint32_t stage32 = smem_u32(stage);

    const float4* __restrict__ src =
        FIRST ? reinterpret_cast<const float4*>(src_ext)
              : reinterpret_cast<const float4*>(g_z1);
    float* __restrict__ zout = FIRST ? g_z1 : g_z2;

    const int t4 = lane & 3;
    const int nrow = lane >> 2;
    const int q = lane & 3;
    const int grp = lane >> 2;

    // ---- B fragments in registers (hi & lo) — tile-invariant ----
    uint32_t bh[KS][2][2], bl[KS][2][2];
#pragma unroll
    for (int j = 0; j < KS; ++j) {
#pragma unroll
        for (int nf = 0; nf < 2; ++nf) {
            int n = nf * 8 + nrow;
            int k0 = t4 * 2;
            float w00 = __ldg(w + ((k0 + 0) * CC + n) * KS + j);
            float w01 = __ldg(w + ((k0 + 1) * CC + n) * KS + j);
            float w10 = __ldg(w + ((k0 + 8) * CC + n) * KS + j);
            float w11 = __ldg(w + ((k0 + 9) * CC + n) * KS + j);
            uint lo;
            bh[j][nf][0] = packhl(w00, w01, lo); bl[j][nf][0] = lo;
            bh[j][nf][1] = packhl(w10, w11, lo); bl[j][nf][1] = lo;
        }
    }

    if (!FIRST) {
        if (tid < CC) {
            float mean = g_stats[tid] * invN;
            float var = g_stats[16 + tid] * invN - mean * mean;
            float a = __ldg(gamma + tid) * rsqrtf(var + 1e-5f);
            coefA[tid] = a;
            coefC[tid] = fmaf(-mean, a, __ldg(beta + tid));
        }
        __syncthreads();
    }

    // per-lane BN coeffs for source channels 4q..4q+3 (conv2 only)
    float a1v[4], c1v[4];
    if (!FIRST) {
#pragma unroll
        for (int k = 0; k < 4; ++k) { a1v[k] = coefA[4 * q + k]; c1v[k] = coefC[4 * q + k]; }
    }
    float bia[4] = {0, 0, 0, 0};
    if (FIRST) {
        bia[0] = __ldg(bias + 2 * t4);
        bia[1] = __ldg(bias + 2 * t4 + 1);
        bia[2] = __ldg(bias + 2 * t4 + 8);
        bia[3] = __ldg(bias + 2 * t4 + 9);
    }

    // ldmatrix per-lane offset within a CH-strided chunk (verified xor layout)
    const uint32_t lr = lane & 15;
    const uint32_t lseg = (uint32_t)(lane >> 4) ^ ((lr >> 2) & 1);
    const uint32_t lmoff = lr * 32 + lseg * 16;

    float s[4] = {0, 0, 0, 0}, qq[4] = {0, 0, 0, 0};
    const unsigned indmax = (unsigned)N * KS - 1u;
    const int wstep = GRID_CONV * WPC;

    int t = blockIdx.x * WPC + wid;
    int iv[5];
    if (t < ntiles) {
#pragma unroll
        for (int i = 0; i < 5; ++i) {
            unsigned u = (unsigned)(i * 32 + lane);
            unsigned off = (unsigned)(t * 16) * KS + (u < 144u ? u : 0u);
            iv[i] = __ldg(ind + (off <= indmax ? off : indmax));
        }
    }

    for (; t < ntiles; t += wstep) {
        const int base = t * 16;

        // ---- gather+split+STS, 2 batches of 9 (MLP=9) ----
#pragma unroll
        for (int b = 0; b < 2; ++b) {
            int idx[9];
#pragma unroll
            for (int k = 0; k < 9; ++k) {
                int i = b * 9 + k;
                idx[k] = __shfl_sync(0xffffffffu, iv[i >> 2], ((i & 3) << 3) + grp);
            }
            float4 v[9];
#pragma unroll
            for (int k = 0; k < 9; ++k)
                v[k] = __ldg(src + (size_t)(unsigned)idx[k] * 4 + q);
#pragma unroll
            for (int k = 0; k < 9; ++k) {
                float4 x = v[k];
                if (!FIRST) {
                    x.x = leaky(fmaf(a1v[0], x.x, c1v[0]));
                    x.y = leaky(fmaf(a1v[1], x.y, c1v[1]));
                    x.z = leaky(fmaf(a1v[2], x.z, c1v[2]));
                    x.w = leaky(fmaf(a1v[3], x.w, c1v[3]));
                }
                uint2 hi, lo;
                split4(x, hi, lo);
                int u = (b * 9 + k) * 8 + grp;
                int pt = (u * 57) >> 9;        // u/9
                int j = u - pt * 9;
                uint32_t p = ((uint32_t)pt >> 2) & 1u;
                uint32_t off = (uint32_t)j * CH + (uint32_t)pt * 32u +
                               (((uint32_t)q * 8u) ^ (p << 4));
                *reinterpret_cast<uint2*>(stage + off) = hi;
                *reinterpret_cast<uint2*>(stage + 9 * CH + off) = lo;
            }
        }

        // ---- prefetch next tile's indices (overlaps MMA latency) ----
        int tn = t + wstep;
        int ivn[5];
        if (tn < ntiles) {
#pragma unroll
            for (int i = 0; i < 5; ++i) {
                unsigned u = (unsigned)(i * 32 + lane);
                unsigned off = (unsigned)(tn * 16) * KS + (u < 144u ? u : 0u);
                ivn[i] = __ldg(ind + (off <= indmax ? off : indmax));
            }
        }
        __syncwarp();

        // ---- MMA: 9 chunks x (Ahi*Bhi + Ahi*Blo + Alo*Bhi) x 2 n-frags ----
        float c0[4] = {0, 0, 0, 0}, c1[4] = {0, 0, 0, 0};
#pragma unroll
        for (int j = 0; j < KS; ++j) {
            uint32_t ah[4], al[4];
            ldsm4(ah, stage32 + (uint32_t)j * CH + lmoff);
            ldsm4(al, stage32 + (uint32_t)(9 + j) * CH + lmoff);
            mma16816(c0, ah, bh[j][0][0], bh[j][0][1]);
            mma16816(c1, ah, bh[j][1][0], bh[j][1][1]);
            mma16816(c0, ah, bl[j][0][0], bl[j][0][1]);
            mma16816(c1, ah, bl[j][1][0], bl[j][1][1]);
            mma16816(c0, al, bh[j][0][0], bh[j][0][1]);
            mma16816(c1, al, bh[j][1][0], bh[j][1][1]);
        }

        // ---- epilogue: bias, z store, stats ----
        int pA = base + nrow;
        int pB = pA + 8;
        float zA0 = c0[0] + bia[0], zA1 = c0[1] + bia[1];
        float zA2 = c1[0] + bia[2], zA3 = c1[1] + bia[3];
        float zB0 = c0[2] + bia[0], zB1 = c0[3] + bia[1];
        float zB2 = c1[2] + bia[2], zB3 = c1[3] + bia[3];

        if (pA < N) {
            float* zr = zout + (size_t)pA * CC + 2 * t4;
            reinterpret_cast<float2*>(zr)[0] = make_float2(zA0, zA1);
            reinterpret_cast<float2*>(zr + 8)[0] = make_float2(zA2, zA3);
            s[0] += zA0; s[1] += zA1; s[2] += zA2; s[3] += zA3;
            qq[0] += zA0 * zA0; qq[1] += zA1 * zA1; qq[2] += zA2 * zA2; qq[3] += zA3 * zA3;
        }
        if (pB < N) {
            float* zr = zout + (size_t)pB * CC + 2 * t4;
            reinterpret_cast<float2*>(zr)[0] = make_float2(zB0, zB1);
            reinterpret_cast<float2*>(zr + 8)[0] = make_float2(zB2, zB3);
            s[0] += zB0; s[1] += zB1; s[2] += zB2; s[3] += zB3;
            qq[0] += zB0 * zB0; qq[1] += zB1 * zB1; qq[2] += zB2 * zB2; qq[3] += zB3 * zB3;
        }

#pragma unroll
        for (int i = 0; i < 5; ++i) iv[i] = ivn[i];
        __syncwarp();
    }

    // ---- stats: butterfly over lanes sharing t4, then 4 atomics/lane ----
#pragma unroll
    for (int off = 4; off <= 16; off <<= 1) {
#pragma unroll
        for (int k = 0; k < 4; ++k) {
            s[k] += __shfl_xor_sync(0xffffffffu, s[k], off);
            qq[k] += __shfl_xor_sync(0xffffffffu, qq[k], off);
        }
    }
    if (lane < 4) {
        const int soff = FIRST ? 0 : 32;
        int ch[4] = {2 * lane, 2 * lane + 1, 2 * lane + 8, 2 * lane + 9};
#pragma unroll
        for (int k = 0; k < 4; ++k) {
            atomicAdd(&g_stats[soff + ch[k]], s[k]);
            atomicAdd(&g_stats[soff + 16 + ch[k]], qq[k]);
        }
    }
}

// ---------------------------------------------------------------------------
// k3: out = leaky(bn2(z2) + data)
// ---------------------------------------------------------------------------
__global__ __launch_bounds__(256) void k3_epilogue(
    const float* __restrict__ data, const float* __restrict__ gamma2,
    const float* __restrict__ beta2, float* __restrict__ out, int N, float invN)
{
    __shared__ float a2s[CC], c2s[CC];
    if (threadIdx.x < CC) {
        int o = threadIdx.x;
        float mean = g_stats[32 + o] * invN;
        float var = g_stats[48 + o] * invN - mean * mean;
        float a = gamma2[o] * rsqrtf(var + 1e-5f);
        a2s[o] = a;
        c2s[o] = fmaf(-mean, a, beta2[o]);
    }
    __syncthreads();
    int total4 = N * 4;
    const float4* z4 = reinterpret_cast<const float4*>(g_z2);
    const float4* d4 = reinterpret_cast<const float4*>(data);
    float4* o4 = reinterpret_cast<float4*>(out);
    for (int i = blockIdx.x * blockDim.x + threadIdx.x; i < total4;
         i += gridDim.x * blockDim.x) {
        float4 zv = z4[i];
        float4 dv = d4[i];
        int cb = (i & 3) * 4;
        float4 r;
        r.x = leaky(fmaf(a2s[cb + 0], zv.x, c2s[cb + 0]) + dv.x);
        r.y = leaky(fmaf(a2s[cb + 1], zv.y, c2s[cb + 1]) + dv.y);
        r.z = leaky(fmaf(a2s[cb + 2], zv.z, c2s[cb + 2]) + dv.z);
        r.w = leaky(fmaf(a2s[cb + 3], zv.w, c2s[cb + 3]) + dv.w);
        o4[i] = r;
    }
}

extern "C" void kernel_launch(void* const* d_in, const int* in_sizes, int n_in,
                              void* d_out, int out_size)
{
    const float* data   = (const float*)d_in[0];
    const int*   ind    = (const int*)d_in[1];
    const float* w1     = (const float*)d_in[2];
    const float* b1     = (const float*)d_in[3];
    const float* gamma1 = (const float*)d_in[4];
    const float* beta1  = (const float*)d_in[5];
    const float* w2     = (const float*)d_in[6];
    const float* gamma2 = (const float*)d_in[7];
    const float* beta2  = (const float*)d_in[8];

    int N = in_sizes[0] / CC;
    if (N > NMAX) N = NMAX;
    float invN = 1.0f / (float)N;
    int ntiles = (N + 15) / 16;

    k0_zero<<<1, 64>>>();
    conv_mma<true><<<GRID_CONV, TPB, SMEM_BYTES>>>(
        data, ind, w1, b1, nullptr, nullptr, N, ntiles, invN);
    conv_mma<false><<<GRID_CONV, TPB, SMEM_BYTES>>>(
        data, ind, w2, nullptr, gamma1, beta1, N, ntiles, invN);
    k3_epilogue<<<1024, 256>>>(data, gamma2, beta2, (float*)d_out, N, invN);
}